// round 3
// baseline (speedup 1.0000x reference)
#include <cuda_runtime.h>
#include <math.h>

#define B_N 1024
#define F_N 257
#define BF_N (B_N * F_N)
#define T_CORE 130
#define NBX 2
#define NPART (NBX * B_N)   // 2048
#define NT 136              // padded token slots per block

typedef unsigned long long u64;

// -------- device scratch (allocation-free) --------
__device__ __align__(16) float g_h[2][(size_t)BF_N * 32];
__device__ __align__(16) float g_c[(size_t)BF_N * 32];
__device__ __align__(16) float g_part[NPART][64];
__device__ __align__(16) float g_bn[2][32];

__device__ __forceinline__ float gelu_f(float x) {
    return 0.5f * x * (1.0f + erff(x * 0.70710678118654752440f));
}
__device__ __forceinline__ void ffma2(u64& d, u64 a, u64 b) {
    asm("fma.rn.f32x2 %0, %1, %2, %0;" : "+l"(d) : "l"(a), "l"(b));
}
__device__ __forceinline__ u64 pack2(float x) {
    u64 r; asm("mov.b64 %0, {%1, %1};" : "=l"(r) : "f"(x)); return r;
}
__device__ __forceinline__ float2 unpack2(u64 a) {
    float2 f; asm("mov.b64 {%0, %1}, %2;" : "=f"(f.x), "=f"(f.y) : "l"(a)); return f;
}

// ===== conv (width-3 over F) on smem y [NT][36] + BN partials; all threads must call =====
__device__ __forceinline__ void conv_phase(const float* y, const float* cws,
                                           int fb, int E, size_t rowbase,
                                           int pidx, float* red) {
    int tid = threadIdx.x;
    int tq = tid >> 2, o0 = (tid & 3) << 3;
    float s1[8], s2[8];
#pragma unroll
    for (int j = 0; j < 8; j++) { s1[j] = 0.f; s2[j] = 0.f; }
#pragma unroll
    for (int it = 0; it < 3; it++) {
        int t = it * 64 + tq;
        if (t < E) {
            int f = fb + t;
            int s = t + 1;  // y slot for global token f
            u64 acc2[4] = {0ull, 0ull, 0ull, 0ull};
#pragma unroll
            for (int w = 0; w < 3; w++) {
                if (w == 0 && f == 0) continue;
                if (w == 2 && f == F_N - 1) continue;
                const float* yr = y + (s - 1 + w) * 36;
                const float* wb = cws + w * 1024 + o0;
#pragma unroll
                for (int i = 0; i < 32; i++) {
                    u64 a2 = pack2(yr[i]);
                    const u64* wr = (const u64*)(wb + i * 32);
                    ffma2(acc2[0], a2, wr[0]);
                    ffma2(acc2[1], a2, wr[1]);
                    ffma2(acc2[2], a2, wr[2]);
                    ffma2(acc2[3], a2, wr[3]);
                }
            }
            ulonglong2* co = (ulonglong2*)&g_c[(rowbase + f) * 32 + o0];
            co[0] = make_ulonglong2(acc2[0], acc2[1]);
            co[1] = make_ulonglong2(acc2[2], acc2[3]);
#pragma unroll
            for (int k = 0; k < 4; k++) {
                float2 f2 = unpack2(acc2[k]);
                s1[2 * k] += f2.x;     s2[2 * k] += f2.x * f2.x;
                s1[2 * k + 1] += f2.y; s2[2 * k + 1] += f2.y * f2.y;
            }
        }
    }
#pragma unroll
    for (int off = 4; off < 32; off <<= 1) {
#pragma unroll
        for (int j = 0; j < 8; j++) {
            s1[j] += __shfl_xor_sync(0xffffffffu, s1[j], off);
            s2[j] += __shfl_xor_sync(0xffffffffu, s2[j], off);
        }
    }
    int warp = tid >> 5, lane = tid & 31;
    if (lane < 4) {
#pragma unroll
        for (int j = 0; j < 8; j++) {
            red[((warp * 4 + lane) * 8 + j) * 2 + 0] = s1[j];
            red[((warp * 4 + lane) * 8 + j) * 2 + 1] = s2[j];
        }
    }
    __syncthreads();
    if (tid < 64) {
        int kind = tid >> 5, ch = tid & 31;
        int sl = ch >> 3, j = ch & 7;
        float v = 0.f;
#pragma unroll
        for (int w2 = 0; w2 < 8; w2++) v += red[((w2 * 4 + sl) * 8 + j) * 2 + kind];
        g_part[pidx][kind * 32 + ch] = v;
    }
}

// ===== k_pre: inproj (18->32) + conv layer-0 + partials =====
__global__ __launch_bounds__(256, 2) void k_pre(const float* __restrict__ x,
                                                const float* __restrict__ in_w,
                                                const float* __restrict__ in_b,
                                                const float* __restrict__ cw0) {
    __shared__ __align__(16) float xs[2584];   // [s][19]
    __shared__ __align__(16) float yb[4896];   // [NT][36]
    __shared__ __align__(16) float wsin[576];
    __shared__ __align__(16) float bsin[32];
    __shared__ __align__(16) float cw[3072];
    int tid = threadIdx.x;
    int fb = blockIdx.x * T_CORE;
    int E = min(T_CORE, F_N - fb);
    size_t rowbase = (size_t)blockIdx.y * F_N;

    for (int idx = tid; idx < (E + 2) * 18; idx += 256) {
        int s = idx / 18, i = idx - s * 18;
        int f = fb - 1 + s;
        xs[s * 19 + i] = (f >= 0 && f < F_N) ? x[(rowbase + f) * 18 + i] : 0.f;
    }
    for (int idx = tid; idx < 576; idx += 256) wsin[idx] = in_w[idx];
    if (tid < 32) bsin[tid] = in_b[tid];
    for (int idx = tid; idx < 3072; idx += 256) cw[idx] = cw0[idx];
    __syncthreads();

    int s = tid;
    if (s < E + 2) {
        int f = fb - 1 + s;
        u64 acc[16];
        if (f >= 0 && f < F_N) {
            const u64* b2 = (const u64*)bsin;
#pragma unroll
            for (int k = 0; k < 16; k++) acc[k] = b2[k];
#pragma unroll
            for (int i = 0; i < 18; i++) {
                u64 a2 = pack2(xs[s * 19 + i]);
                const u64* wr = (const u64*)(wsin + i * 32);
#pragma unroll
                for (int k = 0; k < 16; k++) ffma2(acc[k], a2, wr[k]);
            }
        } else {
#pragma unroll
            for (int k = 0; k < 16; k++) acc[k] = 0ull;
        }
        ulonglong2* o = (ulonglong2*)&yb[s * 36];
#pragma unroll
        for (int k = 0; k < 8; k++) o[k] = make_ulonglong2(acc[2 * k], acc[2 * k + 1]);
    }
    __syncthreads();

    for (int idx = tid; idx < E * 32; idx += 256) {
        int t = idx >> 5, c = idx & 31;
        g_h[0][(rowbase + fb + t) * 32 + c] = yb[(t + 1) * 36 + c];
    }
    conv_phase(yb, cw, fb, E, rowbase, (int)blockIdx.y * NBX + blockIdx.x, xs);
}

// ===== BN finalize: one block per channel =====
__global__ __launch_bounds__(256) void k_bnfin(const float* __restrict__ bng,
                                               const float* __restrict__ bnb) {
    __shared__ float rs[256], rq[256];
    int c = blockIdx.x;
    float s = 0.f, q = 0.f;
    for (int i = threadIdx.x; i < NPART; i += 256) {
        s += g_part[i][c];
        q += g_part[i][32 + c];
    }
    rs[threadIdx.x] = s; rq[threadIdx.x] = q;
    __syncthreads();
    for (int off = 128; off > 0; off >>= 1) {
        if (threadIdx.x < off) {
            rs[threadIdx.x] += rs[threadIdx.x + off];
            rq[threadIdx.x] += rq[threadIdx.x + off];
        }
        __syncthreads();
    }
    if (threadIdx.x == 0) {
        float mean = rs[0] * (1.0f / BF_N);
        float var = rq[0] * (1.0f / BF_N) - mean * mean;
        float a = rsqrtf(var + 1e-5f) * bng[c];
        g_bn[0][c] = a;
        g_bn[1][c] = bnb[c] - mean * a;
    }
}

// ===== fused layer: kv GEMM + banded attn (q on-the-fly) + proj + BN/GELU + LN + next-conv =====
// smem floats: R1(ht[32][136] / y[NT][36]) 4896 | kv[NT][68] 9248 | as_[NT][33] 4488 (also conv red)
//              | wq 3072 | wp 1024 | cw 3072 | params 160   => 25960 floats = 103,840 B
#define SMEM_APPLY (25960 * 4)
__global__ __launch_bounds__(256, 2) void k_apply(const float* __restrict__ qw,
                                                  const float* __restrict__ pw,
                                                  const float* __restrict__ pbias,
                                                  const float* __restrict__ lng,
                                                  const float* __restrict__ lnb,
                                                  const float* __restrict__ cwn,
                                                  int src, int last) {
    extern __shared__ float sm[];
    float* R1 = sm;            // ht [32][136] then y [NT][36]
    float* kv = sm + 4896;     // [NT][68]: k at +0, v at +32
    float* as_ = kv + 9248;    // [NT][33]; reused as conv reduction area
    float* wq = as_ + 4488;    // 32x96
    float* wp = wq + 3072;     // 32x32
    float* cw = wp + 1024;     // 3x32x32
    float* pb = cw + 3072;
    float* lg = pb + 32;
    float* lb = lg + 32;
    float* bna = lb + 32;
    float* bnb = bna + 32;

    int tid = threadIdx.x;
    int fb = blockIdx.x * T_CORE;
    int E = min(T_CORE, F_N - fb);
    size_t rowbase = (size_t)blockIdx.y * F_N;
    const float* hsrc = g_h[src];
    float* hdst = g_h[src ^ 1];
    float* ht = R1;
    float* y = R1;

    // ---- stage h (channel-major) + weights ----
    for (int idx = tid; idx < 32 * NT; idx += 256) {
        int t = idx >> 5, c = idx & 31;
        int f = fb - 1 + t;
        float v = (f >= 0 && f < F_N) ? hsrc[(rowbase + f) * 32 + c] : 0.f;
        ht[c * NT + t] = v;
    }
    for (int idx = tid; idx < 3072; idx += 256) wq[idx] = qw[idx];
    for (int idx = tid; idx < 1024; idx += 256) wp[idx] = pw[idx];
    if (!last)
        for (int idx = tid; idx < 3072; idx += 256) cw[idx] = cwn[idx];
    if (tid < 32) {
        pb[tid] = pbias[tid]; lg[tid] = lng[tid]; lb[tid] = lnb[tid];
        bna[tid] = g_bn[0][tid]; bnb[tid] = g_bn[1][tid];
    }
    __syncthreads();

    // ---- Phase B: kv GEMM (NT tokens x 64 ch, K=32), 4 tok x 8 ch, FFMA2 ----
    for (int sl = tid; sl < 272; sl += 256) {
        int og = sl / 34, tg = sl - og * 34;
        int t0 = tg * 4, oc = og * 8;
        u64 acc2[4][4];
#pragma unroll
        for (int a = 0; a < 4; a++)
#pragma unroll
            for (int k = 0; k < 4; k++) acc2[a][k] = 0ull;
#pragma unroll
        for (int i = 0; i < 32; i++) {
            float4 av = *reinterpret_cast<const float4*>(&ht[i * NT + t0]);
            const u64* wr = reinterpret_cast<const u64*>(&wq[i * 96 + 32 + oc]);
            u64 w0 = wr[0], w1 = wr[1], w2 = wr[2], w3 = wr[3];
            u64 a0 = pack2(av.x), a1 = pack2(av.y), a2 = pack2(av.z), a3 = pack2(av.w);
            ffma2(acc2[0][0], a0, w0); ffma2(acc2[0][1], a0, w1); ffma2(acc2[0][2], a0, w2); ffma2(acc2[0][3], a0, w3);
            ffma2(acc2[1][0], a1, w0); ffma2(acc2[1][1], a1, w1); ffma2(acc2[1][2], a1, w2); ffma2(acc2[1][3], a1, w3);
            ffma2(acc2[2][0], a2, w0); ffma2(acc2[2][1], a2, w1); ffma2(acc2[2][2], a2, w2); ffma2(acc2[2][3], a2, w3);
            ffma2(acc2[3][0], a3, w0); ffma2(acc2[3][1], a3, w1); ffma2(acc2[3][2], a3, w2); ffma2(acc2[3][3], a3, w3);
        }
#pragma unroll
        for (int a = 0; a < 4; a++) {
            ulonglong2* dst = reinterpret_cast<ulonglong2*>(&kv[(t0 + a) * 68 + oc]);
            dst[0] = make_ulonglong2(acc2[a][0], acc2[a][1]);
            dst[1] = make_ulonglong2(acc2[a][2], acc2[a][3]);
        }
    }
    __syncthreads();

    // ---- Phase C: q on-the-fly + banded softmax + V-mix ----
    int warp = tid >> 5, lane = tid & 31;
    for (int rep = 0; rep < 17; rep++) {
        int s = rep * 8 + warp;
        if (s >= E + 2) break;
        int f = fb - 1 + s;
        if (f >= 0 && f < F_N) {
            float q = 0.f;
#pragma unroll
            for (int i = 0; i < 32; i++) q += ht[i * NT + s] * wq[i * 96 + lane];
            float sc[3];
#pragma unroll
            for (int j = 0; j < 3; j++) {
                float p = q * kv[(s + j) * 68 + lane];
                p += __shfl_xor_sync(0xffffffffu, p, 1);
                p += __shfl_xor_sync(0xffffffffu, p, 2);
                p += __shfl_xor_sync(0xffffffffu, p, 4);
                sc[j] = (f + j < F_N) ? p * 0.35355339059327373f : -INFINITY;
            }
            float m = fmaxf(sc[0], fmaxf(sc[1], sc[2]));
            float e0 = __expf(sc[0] - m);
            float e1 = (f + 1 < F_N) ? __expf(sc[1] - m) : 0.f;
            float e2 = (f + 2 < F_N) ? __expf(sc[2] - m) : 0.f;
            float inv = 1.f / (e0 + e1 + e2);
            float ao = (e0 * kv[s * 68 + 32 + lane]
                      + e1 * kv[(s + 1) * 68 + 32 + lane]
                      + e2 * kv[(s + 2) * 68 + 32 + lane]) * inv;
            as_[s * 33 + lane] = ao;
        } else {
            as_[s * 33 + lane] = 0.f;
        }
    }
    __syncthreads();

    // ---- Phase D: proj + BN(c)/GELU + residual -> y (overwrites ht) ----
    for (int sl = tid; sl < (E + 2) * 4; sl += 256) {
        int s = sl >> 2, o0 = (sl & 3) << 3;
        int f = fb - 1 + s;
        if (f >= 0 && f < F_N) {
            u64 acc2[4];
            const u64* pb2 = (const u64*)(pb + o0);
            acc2[0] = pb2[0]; acc2[1] = pb2[1]; acc2[2] = pb2[2]; acc2[3] = pb2[3];
#pragma unroll
            for (int i = 0; i < 32; i++) {
                u64 a2 = pack2(as_[s * 33 + i]);
                const u64* wr = (const u64*)(wp + i * 32 + o0);
                ffma2(acc2[0], a2, wr[0]);
                ffma2(acc2[1], a2, wr[1]);
                ffma2(acc2[2], a2, wr[2]);
                ffma2(acc2[3], a2, wr[3]);
            }
            const float4* cg = (const float4*)&g_c[(rowbase + f) * 32 + o0];
            float4 c0 = cg[0], c1 = cg[1];
            float cv[8] = {c0.x, c0.y, c0.z, c0.w, c1.x, c1.y, c1.z, c1.w};
            float yv[8];
#pragma unroll
            for (int k = 0; k < 4; k++) {
                float2 pa = unpack2(acc2[k]);
                float cn0 = cv[2 * k] * bna[o0 + 2 * k] + bnb[o0 + 2 * k];
                float cn1 = cv[2 * k + 1] * bna[o0 + 2 * k + 1] + bnb[o0 + 2 * k + 1];
                yv[2 * k] = gelu_f(cn0) + pa.x;
                yv[2 * k + 1] = gelu_f(cn1) + pa.y;
            }
            float4* yo = (float4*)&y[s * 36 + o0];
            yo[0] = make_float4(yv[0], yv[1], yv[2], yv[3]);
            yo[1] = make_float4(yv[4], yv[5], yv[6], yv[7]);
        } else {
            float4* yo = (float4*)&y[s * 36 + o0];
            yo[0] = make_float4(0.f, 0.f, 0.f, 0.f);
            yo[1] = make_float4(0.f, 0.f, 0.f, 0.f);
        }
    }
    __syncthreads();

    // ---- Phase E: LayerNorm in place ----
    for (int rep = 0; rep < 17; rep++) {
        int s = rep * 8 + warp;
        if (s >= E + 2) break;
        int f = fb - 1 + s;
        if (f >= 0 && f < F_N) {
            float yv = y[s * 36 + lane];
            float su = yv;
#pragma unroll
            for (int off = 1; off < 32; off <<= 1) su += __shfl_xor_sync(0xffffffffu, su, off);
            float mean = su * (1.f / 32.f);
            float d = yv - mean;
            float v = d * d;
#pragma unroll
            for (int off = 1; off < 32; off <<= 1) v += __shfl_xor_sync(0xffffffffu, v, off);
            y[s * 36 + lane] = d * rsqrtf(v * (1.f / 32.f) + 1e-5f) * lg[lane] + lb[lane];
        }
    }
    __syncthreads();

    // ---- write h_{l+1} (core) + next-layer conv ----
    for (int idx = tid; idx < E * 32; idx += 256) {
        int t = idx >> 5, c = idx & 31;
        hdst[(rowbase + fb + t) * 32 + c] = y[(t + 1) * 36 + c];
    }
    if (!last)
        conv_phase(y, cw, fb, E, rowbase, (int)blockIdx.y * NBX + blockIdx.x, as_);
}

// ===== head: gelu(h@W1+b1) @ W2 + b2 -> sigmoid =====
__global__ __launch_bounds__(256) void k_head(const float* __restrict__ w1,
                                              const float* __restrict__ b1,
                                              const float* __restrict__ w2,
                                              const float* __restrict__ b2,
                                              float* __restrict__ out) {
    __shared__ __align__(16) float hsm[256][33];
    __shared__ __align__(16) float ws1[512];
    __shared__ __align__(16) float wb1[16];
    __shared__ __align__(16) float ws2[16];
    __shared__ float b2s;
    int t0 = blockIdx.x * 256;
    const float* hsrc = g_h[0];
    for (int idx = threadIdx.x; idx < 256 * 32; idx += 256) {
        int tok = idx >> 5, c = idx & 31;
        hsm[tok][c] = hsrc[(size_t)(t0 + tok) * 32 + c];
    }
    for (int idx = threadIdx.x; idx < 512; idx += 256) ws1[idx] = w1[idx];
    if (threadIdx.x < 16) { wb1[threadIdx.x] = b1[threadIdx.x]; ws2[threadIdx.x] = w2[threadIdx.x]; }
    if (threadIdx.x == 0) b2s = b2[0];
    __syncthreads();

    const float* hr = hsm[threadIdx.x];
    u64 s2[8];
    const u64* wb2 = (const u64*)wb1;
#pragma unroll
    for (int k = 0; k < 8; k++) s2[k] = wb2[k];
#pragma unroll
    for (int i = 0; i < 32; i++) {
        u64 a2 = pack2(hr[i]);
        const u64* wr = (const u64*)(ws1 + i * 16);
#pragma unroll
        for (int k = 0; k < 8; k++) ffma2(s2[k], a2, wr[k]);
    }
    float m = b2s;
#pragma unroll
    for (int k = 0; k < 8; k++) {
        float2 f2 = unpack2(s2[k]);
        m += gelu_f(f2.x) * ws2[2 * k] + gelu_f(f2.y) * ws2[2 * k + 1];
    }
    out[t0 + threadIdx.x] = 1.f / (1.f + expf(-m));
}

// ===== launcher =====
extern "C" void kernel_launch(void* const* d_in, const int* in_sizes, int n_in,
                              void* d_out, int out_size) {
    const float* x      = (const float*)d_in[0];
    const float* in_w   = (const float*)d_in[1];
    const float* in_b   = (const float*)d_in[2];
    const float* conv_w = (const float*)d_in[3];
    const float* bn_g   = (const float*)d_in[4];
    const float* bn_b   = (const float*)d_in[5];
    const float* qkv_w  = (const float*)d_in[6];
    const float* proj_w = (const float*)d_in[7];
    const float* proj_b = (const float*)d_in[8];
    const float* ln_g   = (const float*)d_in[9];
    const float* ln_b   = (const float*)d_in[10];
    const float* h1_w   = (const float*)d_in[11];
    const float* h1_b   = (const float*)d_in[12];
    const float* h2_w   = (const float*)d_in[13];
    const float* h2_b   = (const float*)d_in[14];
    float* out = (float*)d_out;

    cudaFuncSetAttribute(k_apply, cudaFuncAttributeMaxDynamicSharedMemorySize, SMEM_APPLY);

    dim3 grid(NBX, B_N);
    // pre: inproj + conv0 + partials
    k_pre<<<grid, 256>>>(x, in_w, in_b, conv_w);
    for (int l = 0; l < 4; l++) {
        int src = l & 1;
        int last = (l == 3) ? 1 : 0;
        k_bnfin<<<32, 256>>>(bn_g + l * 32, bn_b + l * 32);
        k_apply<<<grid, 256, SMEM_APPLY>>>(qkv_w + l * 3072, proj_w + l * 1024,
                                           proj_b + l * 32, ln_g + l * 32, ln_b + l * 32,
                                           conv_w + (l + 1 < 4 ? l + 1 : 0) * 3072,
                                           src, last);
    }
    k_head<<<BF_N / 256, 256>>>(h1_w, h1_b, h2_w, h2_b, out);
}